// round 9
// baseline (speedup 1.0000x reference)
#include <cuda_runtime.h>
#include <cuda_bf16.h>
#include <math.h>

typedef unsigned int u32; typedef unsigned long long u64;
typedef __nv_bfloat16 bf16;

#define MAXN 100096
#define MAXM (3*MAXN)
__device__ float g_dot[(size_t)MAXN*256];
__device__ float g_v2 [(size_t)MAXN*768];          // vec2 fp32 [nd][c][j]
__device__ bf16 g_vh [(size_t)MAXM*256];
__device__ bf16 g_vl [(size_t)MAXM*256];
__device__ bf16 g_hch[(size_t)MAXN*512];
__device__ bf16 g_hcl[(size_t)MAXN*512];
__device__ bf16 g_hh [(size_t)MAXN*256];
__device__ bf16 g_hl [(size_t)MAXN*256];
__device__ bf16 g_Weh[512*256],  g_Wel[512*256];   // [newc][k], pair-interleaved
__device__ bf16 g_W1h[256*512],  g_W1l[256*512];   // [col][k]
__device__ bf16 g_W2h[1024*256], g_W2l[1024*256];  // [newc][k], quad-interleaved+pad

#define RS 20
#define ASTRIDE 2560
#define SMEM_BYTES (8*ASTRIDE*4)   // 80KB: 2 stages x 4 arrays; aliased as fp32 tile in epilogue
#define TS 132                     // epilogue tile row stride (floats)

__device__ __forceinline__ void splt(float f0, float f1, u32 &hi, u32 &lo){
  __nv_bfloat162 h = __floats2bfloat162_rn(f0, f1);
  __nv_bfloat162 l = __floats2bfloat162_rn(f0 - __bfloat162float(h.x),
                                           f1 - __bfloat162float(h.y));
  hi = *(u32*)&h; lo = *(u32*)&l;
}
__device__ __forceinline__ void mma16816(float* d, u32 a0,u32 a1,u32 a2,u32 a3,
                                         u32 b0,u32 b1){
  asm volatile("mma.sync.aligned.m16n8k16.row.col.f32.bf16.bf16.f32 "
    "{%0,%1,%2,%3},{%4,%5,%6,%7},{%8,%9},{%0,%1,%2,%3};"
    : "+f"(d[0]),"+f"(d[1]),"+f"(d[2]),"+f"(d[3])
    : "r"(a0),"r"(a1),"r"(a2),"r"(a3),"r"(b0),"r"(b1));
}
__device__ __forceinline__ u32 s2u(const void* p){ u32 a;
  asm("{.reg .u64 t; cvta.to.shared.u64 t,%1; cvt.u32.u64 %0,t;}":"=r"(a):"l"(p)); return a; }
__device__ __forceinline__ void cpa16(u32 dst, const void* src){
  asm volatile("cp.async.cg.shared.global [%0], [%1], 16;" :: "r"(dst), "l"(src));
}

// MODE 0: G1 (vec @ We_interleaved) -> scalar/dot/vec2 fused epilogue
// MODE 1: G2 (hc @ W1) -> silu -> hh/hl
// MODE 2: G3 (h @ W2_quad) -> dx, dvec fused epilogue
template<int MODE>
__global__ void __launch_bounds__(128, 2)
gemm_k(const bf16* __restrict__ Ah, const bf16* __restrict__ Al,
       const bf16* __restrict__ Bh, const bf16* __restrict__ Bl,
       const float* __restrict__ bias,
       void* o0, void* o1, float* __restrict__ odot, float* __restrict__ ov2,
       int M, int K, int N, int nnodes)
{
  extern __shared__ u32 sm[];
  const u32 sbase = s2u(sm);
  const int tid = threadIdx.x, lane = tid & 31, wid = tid >> 5;
  const int wm = (wid & 1) * 64, wn = (wid >> 1) * 64;
  const int m0 = (MODE == 0) ? blockIdx.y * 126 : blockIdx.y * 128;
  const int n0 = blockIdx.x * 128;
  const int g = lane >> 2, qq = lane & 3;
  const int NK = K >> 5;

  float acc[4][8][4];
  #pragma unroll
  for (int a=0;a<4;a++) for (int b=0;b<8;b++) for (int c=0;c<4;c++) acc[a][b][c]=0.f;

  const int srow = tid >> 2, sc = tid & 3;
  auto stage = [&](int s, int kc){
    #pragma unroll
    for (int q = 0; q < 16; q++){
      const int a   = q >> 2;
      const int row = (q & 3) * 32 + srow;
      const u32 dst = sbase + ((s*4 + a)*ASTRIDE + row*RS + sc*4) * 4;
      const bf16* src;
      if (a < 2){
        int gr = m0 + row; if (gr >= M) gr = M - 1;
        src = (a == 0 ? Ah : Al) + (size_t)gr * K + kc + sc*8;
      } else {
        src = (a == 2 ? Bh : Bl) + (size_t)(n0 + row) * K + kc + sc*8;
      }
      cpa16(dst, src);
    }
    asm volatile("cp.async.commit_group;" ::: "memory");
  };

  stage(0, 0);
  for (int it = 0; it < NK; it++){
    if (it + 1 < NK){
      stage((it + 1) & 1, (it + 1) << 5);
      asm volatile("cp.async.wait_group 1;" ::: "memory");
    } else {
      asm volatile("cp.async.wait_group 0;" ::: "memory");
    }
    __syncthreads();
    const u32* SAh = sm + ((it & 1)*4)*ASTRIDE;
    const u32* SAl = SAh + ASTRIDE;
    const u32* SBh = SAl + ASTRIDE;
    const u32* SBl = SBh + ASTRIDE;
    #pragma unroll
    for (int k16 = 0; k16 < 2; k16++){
      const int kw = k16*8 + qq;
      u32 ah[4][4], al[4][4];
      #pragma unroll
      for (int fm = 0; fm < 4; fm++){
        int rb = (wm + fm*16 + g)*RS + kw, rb8 = rb + 8*RS;
        ah[fm][0]=SAh[rb]; ah[fm][1]=SAh[rb8]; ah[fm][2]=SAh[rb+4]; ah[fm][3]=SAh[rb8+4];
        al[fm][0]=SAl[rb]; al[fm][1]=SAl[rb8]; al[fm][2]=SAl[rb+4]; al[fm][3]=SAl[rb8+4];
      }
      #pragma unroll
      for (int fn = 0; fn < 8; fn++){
        int nb = (wn + fn*8 + g)*RS + kw;
        u32 bh0 = SBh[nb], bh1 = SBh[nb+4];
        u32 bl0 = SBl[nb], bl1 = SBl[nb+4];
        #pragma unroll
        for (int fm = 0; fm < 4; fm++){
          mma16816(acc[fm][fn], ah[fm][0],ah[fm][1],ah[fm][2],ah[fm][3], bh0,bh1);
          mma16816(acc[fm][fn], al[fm][0],al[fm][1],al[fm][2],al[fm][3], bh0,bh1);
          mma16816(acc[fm][fn], ah[fm][0],ah[fm][1],ah[fm][2],ah[fm][3], bl0,bl1);
        }
      }
    }
    __syncthreads();
  }

  if (MODE == 1){
    bf16* Ch = (bf16*)o0; bf16* Cl = (bf16*)o1;
    #pragma unroll
    for (int fm = 0; fm < 4; fm++)
      #pragma unroll
      for (int half = 0; half < 2; half++){
        const int row = m0 + wm + fm*16 + g + half*8;
        if (row >= M) continue;
        #pragma unroll
        for (int fn = 0; fn < 8; fn++){
          const int col = n0 + wn + fn*8 + 2*qq;
          float2 bb = *(const float2*)(bias + col);
          float v0 = acc[fm][fn][half*2]   + bb.x;
          float v1 = acc[fm][fn][half*2+1] + bb.y;
          v0 = v0 / (1.f + __expf(-v0));
          v1 = v1 / (1.f + __expf(-v1));
          u32 h, l; splt(v0, v1, h, l);
          ((u32*)Ch)[((size_t)row*N + col) >> 1] = h;
          ((u32*)Cl)[((size_t)row*N + col) >> 1] = l;
        }
      }
    return;
  }

  // MODE 0 / 2: dump acc tile to smem (fp32, [128][TS]) then fused epilogue
  float* smf = (float*)sm;
  #pragma unroll
  for (int fm = 0; fm < 4; fm++)
    #pragma unroll
    for (int half = 0; half < 2; half++){
      const int row = wm + fm*16 + g + half*8;
      #pragma unroll
      for (int fn = 0; fn < 8; fn++){
        const int col = wn + fn*8 + 2*qq;
        *(float2*)&smf[row*TS + col] =
            make_float2(acc[fm][fn][half*2], acc[fm][fn][half*2+1]);
      }
    }
  __syncthreads();

  if (MODE == 0){
    bf16* hch = (bf16*)o0; bf16* hcl = (bf16*)o1;
    const int nd0 = blockIdx.y * 42;
    for (int id = tid; id < 42*64; id += 128){
      const int nd = id >> 6, j = id & 63;
      const int gnd = nd0 + nd;
      if (gnd >= nnodes) break;
      const float* r0 = smf + (3*nd  )*TS + 2*j;
      const float* r1 = smf + (3*nd+1)*TS + 2*j;
      const float* r2 = smf + (3*nd+2)*TS + 2*j;
      float v10=r0[0], v20=r0[1], v11=r1[0], v21=r1[1], v12=r2[0], v22=r2[1];
      float sc = sqrtf(v10*v10 + v11*v11 + v12*v12);
      float dt = (v10*v20 + v11*v21 + v12*v22) * 0.0625f;
      const int jg = (n0 >> 1) + j;
      bf16 sh = __float2bfloat16_rn(sc);
      hch[(size_t)gnd*512 + 256 + jg] = sh;
      hcl[(size_t)gnd*512 + 256 + jg] = __float2bfloat16_rn(sc - __bfloat162float(sh));
      odot[(size_t)gnd*256 + jg] = dt;
      ov2[((size_t)gnd*3 + 0)*256 + jg] = v20;
      ov2[((size_t)gnd*3 + 1)*256 + jg] = v21;
      ov2[((size_t)gnd*3 + 2)*256 + jg] = v22;
    }
  } else {
    float* out = (float*)o0;
    const float is2 = 0.70710678118654752f;
    for (int id = tid; id < 128*32; id += 128){
      const int nd = id >> 5, j = id & 31;
      const int gnd = m0 + nd;
      if (gnd >= nnodes) break;
      const int jg = (n0 >> 2) + j;
      const float* rr = smf + nd*TS + 4*j;
      float x1 = rr[0] + bias[jg];
      float x2 = rr[1] + bias[256 + jg];
      float x3 = rr[2] + bias[512 + jg];
      out[(size_t)gnd*256 + jg] =
          (x1 + x2 + odot[(size_t)gnd*256 + jg]) * is2;
      float* dv = out + (size_t)nnodes*256 + (size_t)gnd*768;
      const float* v2p = ov2 + (size_t)gnd*768;
      dv[      jg] = x3 * v2p[      jg];
      dv[256 + jg] = x3 * v2p[256 + jg];
      dv[512 + jg] = x3 * v2p[512 + jg];
    }
  }
}

// ---- weight prep ----
__global__ void wconv_e(const float* __restrict__ W, bf16* Wh, bf16* Wl){
  int idx = blockIdx.x*256 + threadIdx.x;            // 256*512
  if (idx >= 256*512) return;
  int k = idx >> 9, nc = idx & 511;
  int j = nc >> 1, c = nc & 1;
  float f = W[k*512 + c*256 + j];
  bf16 h = __float2bfloat16_rn(f);
  Wh[(size_t)nc*256 + k] = h;
  Wl[(size_t)nc*256 + k] = __float2bfloat16_rn(f - __bfloat162float(h));
}
__global__ void wconv_1(const float* __restrict__ W, bf16* Wh, bf16* Wl){
  int idx = blockIdx.x*256 + threadIdx.x;            // 512*256
  if (idx >= 512*256) return;
  int k = idx >> 8, c = idx & 255;
  float f = W[idx];
  bf16 h = __float2bfloat16_rn(f);
  Wh[(size_t)c*512 + k] = h;
  Wl[(size_t)c*512 + k] = __float2bfloat16_rn(f - __bfloat162float(h));
}
__global__ void wconv_2(const float* __restrict__ W, bf16* Wh, bf16* Wl){
  int idx = blockIdx.x*256 + threadIdx.x;            // 256*1024
  if (idx >= 256*1024) return;
  int k = idx >> 10, nc = idx & 1023;
  int j = nc >> 2, c = nc & 3;
  float f = (c < 3) ? W[k*768 + c*256 + j] : 0.f;
  bf16 h = __float2bfloat16_rn(f);
  Wh[(size_t)nc*256 + k] = h;
  Wl[(size_t)nc*256 + k] = __float2bfloat16_rn(f - __bfloat162float(h));
}
// ---- activation prep ----
__global__ void aconv(const float* __restrict__ A, bf16* Ahh, bf16* All, int n4){
  int i = blockIdx.x*256 + threadIdx.x;
  if (i >= n4) return;
  float4 v = ((const float4*)A)[i];
  u32 h0,l0,h1,l1;
  splt(v.x, v.y, h0, l0); splt(v.z, v.w, h1, l1);
  ((uint2*)Ahh)[i] = make_uint2(h0, h1);
  ((uint2*)All)[i] = make_uint2(l0, l1);
}
__global__ void xconv(const float* __restrict__ x, int n){
  int idx = blockIdx.x*256 + threadIdx.x;
  if (idx >= n*64) return;                     // float4 units over [n][256]
  int nd = idx >> 6, q = idx & 63;
  float4 v = ((const float4*)x)[idx];
  u32 h0,l0,h1,l1;
  splt(v.x, v.y, h0, l0); splt(v.z, v.w, h1, l1);
  size_t o = ((size_t)nd*512 + q*4) >> 1;      // uint2 index into [n][512]
  ((uint2*)g_hch)[o >> 1] = make_uint2(h0, h1);
  ((uint2*)g_hcl)[o >> 1] = make_uint2(l0, l1);
}

extern "C" void kernel_launch(void* const* d_in, const int* in_sizes, int n_in,
                              void* d_out, int out_size)
{
  const float* x   = (const float*)d_in[0];
  const float* vec = (const float*)d_in[1];
  const float* We  = (const float*)d_in[3];
  const float* W1  = (const float*)d_in[4];
  const float* b1  = (const float*)d_in[5];
  const float* W2  = (const float*)d_in[6];
  const float* b2  = (const float*)d_in[7];
  float* out = (float*)d_out;
  const int n = in_sizes[0] / 256;
  const int M1 = 3*n;

  float *pdot, *pv2;
  bf16 *pvh,*pvl,*phch,*phcl,*phh,*phl,*pWeh,*pWel,*pW1h,*pW1l,*pW2h,*pW2l;
  cudaGetSymbolAddress((void**)&pdot,g_dot); cudaGetSymbolAddress((void**)&pv2, g_v2);
  cudaGetSymbolAddress((void**)&pvh, g_vh);  cudaGetSymbolAddress((void**)&pvl, g_vl);
  cudaGetSymbolAddress((void**)&phch,g_hch); cudaGetSymbolAddress((void**)&phcl,g_hcl);
  cudaGetSymbolAddress((void**)&phh, g_hh);  cudaGetSymbolAddress((void**)&phl, g_hl);
  cudaGetSymbolAddress((void**)&pWeh,g_Weh); cudaGetSymbolAddress((void**)&pWel,g_Wel);
  cudaGetSymbolAddress((void**)&pW1h,g_W1h); cudaGetSymbolAddress((void**)&pW1l,g_W1l);
  cudaGetSymbolAddress((void**)&pW2h,g_W2h); cudaGetSymbolAddress((void**)&pW2l,g_W2l);

  cudaFuncSetAttribute(gemm_k<0>, cudaFuncAttributeMaxDynamicSharedMemorySize, SMEM_BYTES);
  cudaFuncSetAttribute(gemm_k<1>, cudaFuncAttributeMaxDynamicSharedMemorySize, SMEM_BYTES);
  cudaFuncSetAttribute(gemm_k<2>, cudaFuncAttributeMaxDynamicSharedMemorySize, SMEM_BYTES);

  wconv_e<<<(256*512 +255)/256, 256>>>(We, pWeh, pWel);
  wconv_1<<<(512*256 +255)/256, 256>>>(W1, pW1h, pW1l);
  wconv_2<<<(256*1024+255)/256, 256>>>(W2, pW2h, pW2l);
  aconv<<<((M1*64)+255)/256, 256>>>(vec, pvh, pvl, M1*64);
  xconv<<<((n*64)+255)/256, 256>>>(x, n);

  gemm_k<0><<<dim3(4,(n+41)/42), 128, SMEM_BYTES>>>(
      pvh, pvl, pWeh, pWel, (const float*)0,
      phch, phcl, pdot, pv2, M1, 256, 512, n);
  gemm_k<1><<<dim3(2,(n+127)/128), 128, SMEM_BYTES>>>(
      phch, phcl, pW1h, pW1l, b1,
      phh, phl, (float*)0, (float*)0, n, 512, 256, n);
  gemm_k<2><<<dim3(8,(n+127)/128), 128, SMEM_BYTES>>>(
      phh, phl, pW2h, pW2l, b2,
      out, (void*)0, pdot, pv2, n, 256, 1024, n);
}